// round 13
// baseline (speedup 1.0000x reference)
#include <cuda_runtime.h>

// out[b, o, f] = sum_t x[b, t, f] * W[f, o, t] + bias[f, o],  f < TGT=2
// x: (4096, 24, 256) f32   W: (256, 24, 24) f32   bias: (256, 24) f32
// out: (4096, 24, 2) f32 -> float2 out2[b*24 + o]
//
// CONVERGED (rounds 1-12). Wall 6.62-7.04us over 9 samples; mode 6.62us.
// Mechanism:
//  - cooperative gather: exactly ONE LDG.64 per thread, every lane a
//    distinct 128B line (front 8B of each 1KB x row). Per-thread
//    duplicated-LDG variants (24 LDG/thread) cost +2.3us in the L2-hot
//    timed run regardless of register budget -> L1tex wavefront
//    throughput is the binding on-chip resource.
//  - W staged once per block, transposed+interleaved into float4 with
//    stride-13 padding -> phase 2 = 12+12 conflict-free LDS.128 + 48 FMA.
//  - one coalesced STG.64 per thread.
// Timed replays are L2-HOT (proved by R4/R8: cold-ncu flat, wall +2.3us
// -> wall does not track cold kernel). Hence cold-run DRAM-traffic
// levers (TMA gather, L2 promotion control) are dead. Residual wall =
// fixed overhead (~5us: launch ramp T_ovh~5000cyc + graph replay) +
// hot body ~1.6us. Measured dead ends: cp.async (tie), blocks 96-384,
// grids 256-768, barrier-free/shuffle layouts (lose). Search closed.

#define B_DIM 4096
#define T_DIM 24
#define F_DIM 256
#define O_DIM 24
#define NB    8                       // batch rows per block
#define BLOCK 192                     // == NB*T_DIM (1 gather/thread) == NB*O_DIM (1 float2 out/thread)
#define GRID  (B_DIM / NB)            // 512 blocks
#define WJ    12                      // 24 (w0,w1) pairs = 12 float4 per o
#define WPAD  13                      // pad stride to 13 float4 -> conflict-free LDS.128

__global__ __launch_bounds__(BLOCK) void dlinear_kernel(
    const float* __restrict__ x,
    const float* __restrict__ W,
    const float* __restrict__ bias,
    float2* __restrict__ out2)
{
    __shared__ float2 xs[NB * T_DIM];      // xs[b_l*24+t] = (x_f0, x_f1); float4-aliasable
    __shared__ float4 Wq[O_DIM * WPAD];    // Wq[o*13+j] = (W0[2j],W1[2j],W0[2j+1],W1[2j+1])

    const int tid = threadIdx.x;
    const int b0  = blockIdx.x * NB;

    // ---- Phase 1a: gather x — one float2 per thread, distinct 128B line per lane.
    {
        const float2* __restrict__ x2 = (const float2*)x;
        int b_l = tid / T_DIM;
        int t   = tid - b_l * T_DIM;
        xs[tid] = x2[(size_t)((b0 + b_l) * T_DIM + t) * (F_DIM / 2)];
    }

    // ---- Phase 1b (overlapped): stage W transposed. t-pairs are contiguous in
    // the native (f,o,t) layout -> 2 LDG.64 per assembled float4.
    {
        const float2* __restrict__ W0 = (const float2*)W;                    // W[0,:,:]
        const float2* __restrict__ W1 = (const float2*)(W + O_DIM * T_DIM);  // W[1,:,:]
        #pragma unroll
        for (int j = tid; j < O_DIM * WJ; j += BLOCK) {
            int o  = j / WJ;
            int jj = j - o * WJ;              // float2-pair index: t = 2jj, 2jj+1
            float2 a = W0[o * WJ + jj];
            float2 c = W1[o * WJ + jj];
            Wq[o * WPAD + jj] = make_float4(a.x, c.x, a.y, c.y);
        }
    }
    __syncthreads();

    // ---- Phase 2: one float2 output per thread; 12+12 LDS.128 + 48 FMA.
    const int b_l = tid / O_DIM;
    const int o   = tid - b_l * O_DIM;

    const float4* __restrict__ xq = (const float4*)(xs + b_l * T_DIM);  // warp-broadcast
    const float4* __restrict__ wq = Wq + o * WPAD;                      // stride-13 -> conflict-free

    float2 acc = make_float2(__ldg(bias + o), __ldg(bias + O_DIM + o)); // L1-hot broadcast
    #pragma unroll
    for (int j = 0; j < WJ; j++) {
        float4 xv = xq[j];        // (x0[2j], x1[2j], x0[2j+1], x1[2j+1])
        float4 wv = wq[j];        // (w0[2j], w1[2j], w0[2j+1], w1[2j+1])
        acc.x = fmaf(xv.x, wv.x, acc.x);
        acc.y = fmaf(xv.y, wv.y, acc.y);
        acc.x = fmaf(xv.z, wv.z, acc.x);
        acc.y = fmaf(xv.w, wv.w, acc.y);
    }

    out2[(size_t)b0 * O_DIM + tid] = acc;   // coalesced STG.64
}

extern "C" void kernel_launch(void* const* d_in, const int* in_sizes, int n_in,
                              void* d_out, int out_size)
{
    const float* x    = (const float*)d_in[0];
    const float* W    = (const float*)d_in[1];
    const float* bias = (const float*)d_in[2];
    float2* out2 = (float2*)d_out;

    dlinear_kernel<<<GRID, BLOCK>>>(x, W, bias, out2);
}

// round 14
// speedup vs baseline: 1.0386x; 1.0386x over previous
#include <cuda_runtime.h>

// out[b, o, f] = sum_t x[b, t, f] * W[f, o, t] + bias[f, o],  f < TGT=2
// x: (4096, 24, 256) f32   W: (256, 24, 24) f32   bias: (256, 24) f32
// out: (4096, 24, 2) f32 -> float2 out2[b*24 + o]
//
// CONVERGED (rounds 1-13). Wall 6.62-7.04us over 10 samples; mode 6.62us.
// Mechanism:
//  - cooperative gather: exactly ONE LDG.64 per thread, every lane a
//    distinct 128B line (front 8B of each 1KB x row). Per-thread
//    duplicated-LDG variants (24 LDG/thread) cost +2.3us in the L2-hot
//    timed run regardless of register budget -> L1tex wavefront
//    throughput is the binding on-chip resource.
//  - W staged once per block, transposed+interleaved into float4 with
//    stride-13 padding -> phase 2 = 12+12 conflict-free LDS.128 + 48 FMA.
//  - one coalesced STG.64 per thread.
// Timed replays are L2-HOT (R4/R8 contrast: cold-ncu flat while wall
// +2.3us). Residual wall = fixed overhead (~5us: launch ramp
// T_ovh~5000cyc + graph replay) + hot body ~1.6us.
// Rejected (measured): per-thread LDG (+2.3us x2), cp.async (tie),
// blocks 192/256/384, grids 256-768, smem-free W (L1tex flood).
// Rejected (costed): __syncwarp row-private layout (W-stage barrier
// survives), BLOCK=96/grid=1024 (doubles W-staging LDGs), TMA/L2
// promotion (only moves cold-run traffic the timed run doesn't pay).

#define B_DIM 4096
#define T_DIM 24
#define F_DIM 256
#define O_DIM 24
#define NB    8                       // batch rows per block
#define BLOCK 192                     // == NB*T_DIM (1 gather/thread) == NB*O_DIM (1 float2 out/thread)
#define GRID  (B_DIM / NB)            // 512 blocks
#define WJ    12                      // 24 (w0,w1) pairs = 12 float4 per o
#define WPAD  13                      // pad stride to 13 float4 -> conflict-free LDS.128

__global__ __launch_bounds__(BLOCK) void dlinear_kernel(
    const float* __restrict__ x,
    const float* __restrict__ W,
    const float* __restrict__ bias,
    float2* __restrict__ out2)
{
    __shared__ float2 xs[NB * T_DIM];      // xs[b_l*24+t] = (x_f0, x_f1); float4-aliasable
    __shared__ float4 Wq[O_DIM * WPAD];    // Wq[o*13+j] = (W0[2j],W1[2j],W0[2j+1],W1[2j+1])

    const int tid = threadIdx.x;
    const int b0  = blockIdx.x * NB;

    // ---- Phase 1a: gather x — one float2 per thread, distinct 128B line per lane.
    {
        const float2* __restrict__ x2 = (const float2*)x;
        int b_l = tid / T_DIM;
        int t   = tid - b_l * T_DIM;
        xs[tid] = x2[(size_t)((b0 + b_l) * T_DIM + t) * (F_DIM / 2)];
    }

    // ---- Phase 1b (overlapped): stage W transposed. t-pairs are contiguous in
    // the native (f,o,t) layout -> 2 LDG.64 per assembled float4.
    {
        const float2* __restrict__ W0 = (const float2*)W;                    // W[0,:,:]
        const float2* __restrict__ W1 = (const float2*)(W + O_DIM * T_DIM);  // W[1,:,:]
        #pragma unroll
        for (int j = tid; j < O_DIM * WJ; j += BLOCK) {
            int o  = j / WJ;
            int jj = j - o * WJ;              // float2-pair index: t = 2jj, 2jj+1
            float2 a = W0[o * WJ + jj];
            float2 c = W1[o * WJ + jj];
            Wq[o * WPAD + jj] = make_float4(a.x, c.x, a.y, c.y);
        }
    }
    __syncthreads();

    // ---- Phase 2: one float2 output per thread; 12+12 LDS.128 + 48 FMA.
    const int b_l = tid / O_DIM;
    const int o   = tid - b_l * O_DIM;

    const float4* __restrict__ xq = (const float4*)(xs + b_l * T_DIM);  // warp-broadcast
    const float4* __restrict__ wq = Wq + o * WPAD;                      // stride-13 -> conflict-free

    float2 acc = make_float2(__ldg(bias + o), __ldg(bias + O_DIM + o)); // L1-hot broadcast
    #pragma unroll
    for (int j = 0; j < WJ; j++) {
        float4 xv = xq[j];        // (x0[2j], x1[2j], x0[2j+1], x1[2j+1])
        float4 wv = wq[j];        // (w0[2j], w1[2j], w0[2j+1], w1[2j+1])
        acc.x = fmaf(xv.x, wv.x, acc.x);
        acc.y = fmaf(xv.y, wv.y, acc.y);
        acc.x = fmaf(xv.z, wv.z, acc.x);
        acc.y = fmaf(xv.w, wv.w, acc.y);
    }

    out2[(size_t)b0 * O_DIM + tid] = acc;   // coalesced STG.64
}

extern "C" void kernel_launch(void* const* d_in, const int* in_sizes, int n_in,
                              void* d_out, int out_size)
{
    const float* x    = (const float*)d_in[0];
    const float* W    = (const float*)d_in[1];
    const float* bias = (const float*)d_in[2];
    float2* out2 = (float2*)d_out;

    dlinear_kernel<<<GRID, BLOCK>>>(x, W, bias, out2);
}